// round 13
// baseline (speedup 1.0000x reference)
#include <cuda_runtime.h>
#include <cuda_fp16.h>
#include <cstdint>

#define NE 10000
#define NM 2048
#define D  128
#define NEP 10112            // 79*128 padded entity count
#define KSPLIT 8

// ======================= device scratch (no allocations allowed) ============
__device__ unsigned char g_lev[(size_t)NE * NM];   // 0 = no edge, 1..5 relation
__device__ __half g_invh[NE * 8];                  // [i][r] 1/cnt (fp16), r=0 -> 0
__device__ float g_m1[NM * D];                     // relu(x_m @ root1 + b1)
__device__ __half g_ZH[(size_t)5 * 256 * NM];      // [r][n][j] K-major fp16 B
__device__ float g_ebase[(size_t)NE * D];          // x_e @ root1 + b1
__device__ float g_part[(size_t)KSPLIT * NEP * 256];  // K-split partials

// ======================= small PTX helpers ============
#define CP_ASYNC16(s, g) asm volatile("cp.async.cg.shared.global [%0], [%1], 16;" :: "r"(s), "l"(g))
#define CP_COMMIT()      asm volatile("cp.async.commit_group;" ::: "memory")
#define CP_WAIT0()       asm volatile("cp.async.wait_group 0;" ::: "memory")
#define LDSM_X4(r0, r1, r2, r3, a)                                                   \
    asm volatile("ldmatrix.sync.aligned.m8n8.x4.shared.b16 {%0,%1,%2,%3}, [%4];"     \
                 : "=r"(r0), "=r"(r1), "=r"(r2), "=r"(r3) : "r"(a))

__device__ __forceinline__ uint32_t smem_u32(const void* p) {
    uint32_t a;
    asm("{ .reg .u64 t; cvta.to.shared.u64 t, %1; cvt.u32.u64 %0, t; }" : "=r"(a) : "l"(p));
    return a;
}

__device__ __forceinline__ void mma_f16(float* d, const uint32_t* a, uint32_t b0, uint32_t b1) {
    asm volatile(
        "mma.sync.aligned.m16n8k16.row.col.f32.f16.f16.f32 "
        "{%0,%1,%2,%3}, {%4,%5,%6,%7}, {%8,%9}, {%0,%1,%2,%3};"
        : "+f"(d[0]), "+f"(d[1]), "+f"(d[2]), "+f"(d[3])
        : "r"(a[0]), "r"(a[1]), "r"(a[2]), "r"(a[3]), "r"(b0), "r"(b1));
}

// ======================= kernel 1: levels + inverse counts (fp16) ============
__global__ void k_lev(const float* __restrict__ w) {
    int i = blockIdx.x;
    __shared__ int scnt[5];
    if (threadIdx.x < 5) scnt[threadIdx.x] = 0;
    __syncthreads();
    int cnt[5] = {0, 0, 0, 0, 0};
    const float* wr = w + (size_t)i * NM;
    unsigned char* lr = g_lev + (size_t)i * NM;
    #pragma unroll
    for (int s = 0; s < 8; s++) {
        int j = threadIdx.x + s * 256;
        float v = wr[j];
        int lv = (int)ceilf(v * 6.0f) - 1;
        int o = (lv >= 1 && lv <= 5) ? lv : 0;
        lr[j] = (unsigned char)o;
        if (o) cnt[o - 1]++;
    }
    #pragma unroll
    for (int r = 0; r < 5; r++) {
        int v = cnt[r];
        #pragma unroll
        for (int off = 16; off; off >>= 1) v += __shfl_down_sync(0xffffffffu, v, off);
        if ((threadIdx.x & 31) == 0) atomicAdd(&scnt[r], v);
    }
    __syncthreads();
    if (threadIdx.x < 8) {
        float iv = 0.0f;
        if (threadIdx.x >= 1 && threadIdx.x <= 5) {
            int c = scnt[threadIdx.x - 1];
            iv = (c > 0) ? 1.0f / (float)c : 0.0f;
        }
        g_invh[i * 8 + threadIdx.x] = __float2half(iv);
    }
}

// ======================= kernel 2: root1 transform (moles + entities) ========
__global__ void k_root1(const float* __restrict__ xm, const float* __restrict__ xe,
                        const float* __restrict__ root1, const float* __restrict__ b1) {
    __shared__ float xs[128][20];
    int bi = blockIdx.x;
    bool mole = bi < (NM / 16);
    int r0 = mole ? bi * 16 : (bi - NM / 16) * 16;
    const float* src = (mole ? xm : xe) + (size_t)r0 * D;
    int c = threadIdx.x;
    for (int t = c; t < 16 * 128; t += 128) {
        int e = t >> 7, k = t & 127;
        xs[k][e] = src[e * D + k];
    }
    __syncthreads();
    float a[16];
    #pragma unroll
    for (int e = 0; e < 16; e++) a[e] = 0.0f;
    #pragma unroll 2
    for (int k = 0; k < 128; k++) {
        float wv = root1[k * D + c];
        float4 x0 = *(const float4*)&xs[k][0];
        float4 x1 = *(const float4*)&xs[k][4];
        float4 x2 = *(const float4*)&xs[k][8];
        float4 x3 = *(const float4*)&xs[k][12];
        a[0] += x0.x * wv; a[1] += x0.y * wv; a[2] += x0.z * wv; a[3] += x0.w * wv;
        a[4] += x1.x * wv; a[5] += x1.y * wv; a[6] += x1.z * wv; a[7] += x1.w * wv;
        a[8] += x2.x * wv; a[9] += x2.y * wv; a[10] += x2.z * wv; a[11] += x2.w * wv;
        a[12] += x3.x * wv; a[13] += x3.y * wv; a[14] += x3.z * wv; a[15] += x3.w * wv;
    }
    float bb = b1[c];
    if (mole) {
        #pragma unroll
        for (int e = 0; e < 16; e++) g_m1[(size_t)(r0 + e) * D + c] = fmaxf(a[e] + bb, 0.0f);
    } else {
        #pragma unroll
        for (int e = 0; e < 16; e++) g_ebase[(size_t)(r0 + e) * D + c] = a[e] + bb;
    }
}

// ======================= kernel 4: ZH[r][n][j] = fp16 K-major ================
__global__ void k_Z(const float* __restrict__ xm, const float* __restrict__ W1,
                    const float* __restrict__ W2) {
    __shared__ float xs[128][20], ms[128][20];
    int ri = blockIdx.y;
    int j0 = blockIdx.x * 16;
    for (int t = threadIdx.x; t < 16 * 128; t += 256) {
        int e = t >> 7, k = t & 127;
        xs[k][e] = xm[(size_t)(j0 + e) * D + k];
        ms[k][e] = g_m1[(size_t)(j0 + e) * D + k];
    }
    __syncthreads();
    int c = threadIdx.x;
    int cc = c & 127;
    const float* W = ((c < 128) ? W1 : W2) + (size_t)(ri + 1) * D * D;
    const float(*S)[20] = (c < 128) ? xs : ms;
    float a[16];
    #pragma unroll
    for (int e = 0; e < 16; e++) a[e] = 0.0f;
    #pragma unroll 2
    for (int k = 0; k < 128; k++) {
        float wv = W[k * D + cc];
        float4 x0 = *(const float4*)&S[k][0];
        float4 x1 = *(const float4*)&S[k][4];
        float4 x2 = *(const float4*)&S[k][8];
        float4 x3 = *(const float4*)&S[k][12];
        a[0] += x0.x * wv; a[1] += x0.y * wv; a[2] += x0.z * wv; a[3] += x0.w * wv;
        a[4] += x1.x * wv; a[5] += x1.y * wv; a[6] += x1.z * wv; a[7] += x1.w * wv;
        a[8] += x2.x * wv; a[9] += x2.y * wv; a[10] += x2.z * wv; a[11] += x2.w * wv;
        a[12] += x3.x * wv; a[13] += x3.y * wv; a[14] += x3.z * wv; a[15] += x3.w * wv;
    }
    __half2* dst = (__half2*)(g_ZH + ((size_t)ri * 256 + c) * NM + j0);
    #pragma unroll
    for (int e = 0; e < 8; e++) dst[e] = __floats2half2_rn(a[2 * e], a[2 * e + 1]);
}

// ======================= kernel 5: fp16 mask-GEMM, M64 x N256 CTA tile =======
// grid (158, 8): x = M tile (64), y = K eighth (1280). Full N = 256.
// 256 threads, 8 warps: wm = wid&1 (2 x 32 rows), wn = wid>>1 (4 x 64 cols).
// 2 CTAs per SM (regs <= 128, smem 90KB/CTA).
constexpr int KT = 64;
constexpr int KQ = 10240 / KSPLIT;             // 1280
constexpr int ITERS = KQ / KT;                 // 20
constexpr int ASTR = 72;
constexpr int A_H = 64 * ASTR;                 // 4608 halfs
constexpr int B_H = 256 * ASTR;                // 18432 halfs
constexpr int STAGE_H = A_H + B_H;             // 23040 halfs
constexpr int STAGE_B = STAGE_H * 2;           // 46080 bytes
constexpr int SM_MMA_BYTES = 2 * STAGE_B;      // 92160 bytes

__global__ __launch_bounds__(256, 2) void k_mma() {
    extern __shared__ __half smh[];
    uint32_t sbase = smem_u32(smh);

    int tid = threadIdx.x;
    int wid = tid >> 5, lane = tid & 31;
    int gid = lane >> 2, t4 = lane & 3;
    int wm = wid & 1, wn = wid >> 1;

    int i0 = blockIdx.x * 64;
    int kbase = blockIdx.y * KQ;

    // A-build role: row = tid>>2 (0..63), 16-lev-byte chunk aq = tid&3
    int arow = tid >> 2, aq = tid & 3;
    int gr = min(i0 + arow, NE - 1);
    const unsigned char* levrow = g_lev + (size_t)gr * NM;
    const __half* invrow = g_invh + (size_t)gr * 8;

    auto buildA = [&](int s, int r, int j0) {
        unsigned char rv = (unsigned char)(r + 1);
        uint4 u = *(const uint4*)(levrow + j0 + aq * 16);
        unsigned char bts[16];
        *(uint4*)bts = u;
        __half ivh = invrow[r + 1];
        __half z = __ushort_as_half((unsigned short)0);
        uint32_t pk[8];
        #pragma unroll
        for (int q = 0; q < 8; q++) {
            __half2 h2;
            h2.x = (bts[2 * q] == rv) ? ivh : z;
            h2.y = (bts[2 * q + 1] == rv) ? ivh : z;
            pk[q] = *(uint32_t*)&h2;
        }
        uint32_t* dst = (uint32_t*)(smh + s * STAGE_H + arow * ASTR + aq * 16);
        *(uint4*)dst = make_uint4(pk[0], pk[1], pk[2], pk[3]);
        *(uint4*)(dst + 4) = make_uint4(pk[4], pk[5], pk[6], pk[7]);
    };
    auto stageB = [&](int s, int r, int j0) {
        uint32_t sb = sbase + s * STAGE_B + A_H * 2;
        const __half* gb = g_ZH + (size_t)r * 256 * NM + j0;
        #pragma unroll
        for (int h = 0; h < 8; h++) {
            int c = tid + h * 256;
            int n = c >> 3, ch = c & 7;
            uint32_t sa = sb + (uint32_t)(n * (ASTR * 2) + ch * 16);
            CP_ASYNC16(sa, gb + (size_t)n * NM + ch * 8);
        }
        CP_COMMIT();
    };

    uint32_t aAddr[2], bAddr[4];
    #pragma unroll
    for (int mi = 0; mi < 2; mi++) {
        int row = wm * 32 + mi * 16 + (lane & 15);
        aAddr[mi] = sbase + (uint32_t)(row * ASTR + (lane >> 4) * 8) * 2u;
    }
    #pragma unroll
    for (int nj = 0; nj < 4; nj++) {
        int nrow = wn * 64 + nj * 16 + ((lane >> 4) & 1) * 8 + (lane & 7);
        int koff = ((lane >> 3) & 1) * 8;
        bAddr[nj] = sbase + (uint32_t)(A_H * 2) + (uint32_t)(nrow * ASTR + koff) * 2u;
    }

    float dacc[2][8][4];
    #pragma unroll
    for (int mi = 0; mi < 2; mi++)
        #pragma unroll
        for (int ni = 0; ni < 8; ni++)
            #pragma unroll
            for (int q = 0; q < 4; q++) dacc[mi][ni][q] = 0.0f;

    {
        int kg = kbase;
        stageB(0, kg >> 11, kg & 2047);
        buildA(0, kg >> 11, kg & 2047);
    }

    for (int it = 0; it < ITERS; it++) {
        int s = it & 1;
        CP_WAIT0();
        __syncthreads();
        if (it + 1 < ITERS) {
            int kg = kbase + (it + 1) * KT;
            stageB(s ^ 1, kg >> 11, kg & 2047);
            buildA(s ^ 1, kg >> 11, kg & 2047);
        }

        uint32_t soff = (uint32_t)(s * STAGE_B);
        #pragma unroll
        for (int kk = 0; kk < 4; kk++) {
            uint32_t kb = soff + kk * 32;
            uint32_t af[2][4];
            #pragma unroll
            for (int mi = 0; mi < 2; mi++)
                LDSM_X4(af[mi][0], af[mi][1], af[mi][2], af[mi][3], aAddr[mi] + kb);
            #pragma unroll
            for (int nj = 0; nj < 4; nj++) {
                uint32_t r0, r1, r2, r3;
                LDSM_X4(r0, r1, r2, r3, bAddr[nj] + kb);
                #pragma unroll
                for (int mi = 0; mi < 2; mi++) {
                    mma_f16(dacc[mi][2 * nj], af[mi], r0, r1);
                    mma_f16(dacc[mi][2 * nj + 1], af[mi], r2, r3);
                }
            }
        }
        __syncthreads();
    }

    float* dst = g_part + (size_t)blockIdx.y * NEP * 256;
    #pragma unroll
    for (int mi = 0; mi < 2; mi++) {
        int r0 = i0 + wm * 32 + mi * 16 + gid;
        #pragma unroll
        for (int ni = 0; ni < 8; ni++) {
            int cn = wn * 64 + ni * 8 + 2 * t4;
            *(float2*)(dst + (size_t)r0 * 256 + cn) = make_float2(dacc[mi][ni][0], dacc[mi][ni][1]);
            *(float2*)(dst + (size_t)(r0 + 8) * 256 + cn) = make_float2(dacc[mi][ni][2], dacc[mi][ni][3]);
        }
    }
}

// ======================= kernel 6: reduce partials + both conv epilogues =====
constexpr int SM_EPI_BYTES = 64 * 132 * 4;
__global__ __launch_bounds__(256, 1) void k_epi(const float* __restrict__ root2,
                                                const float* __restrict__ b2,
                                                float* __restrict__ out) {
    extern __shared__ float sE1[];   // [64][132]
    int i0 = blockIdx.x * 64;
    int tid = threadIdx.x;

    for (int idx = tid; idx < 64 * 32; idx += 256) {
        int e = idx >> 5, q = idx & 31;
        int i = i0 + e;
        float4 v = make_float4(0, 0, 0, 0);
        if (i < NE) {
            float4 s = *(const float4*)(g_ebase + (size_t)i * D + q * 4);
            #pragma unroll
            for (int z = 0; z < KSPLIT; z++) {
                float4 p = *(const float4*)(g_part + ((size_t)z * NEP + i) * 256 + q * 4);
                s.x += p.x; s.y += p.y; s.z += p.z; s.w += p.w;
            }
            v.x = fmaxf(s.x, 0.0f); v.y = fmaxf(s.y, 0.0f);
            v.z = fmaxf(s.z, 0.0f); v.w = fmaxf(s.w, 0.0f);
        }
        *(float4*)(sE1 + e * 132 + q * 4) = v;
    }
    __syncthreads();

    int pe = tid >> 3, cg = tid & 7;
    int eA = pe * 2, eB = pe * 2 + 1;
    int iA = i0 + eA, iB = i0 + eB;
    int c0 = cg * 16;
    float4 oA[4], oB[4];
    #pragma unroll
    for (int q = 0; q < 4; q++) {
        float4 bb = *(const float4*)(b2 + c0 + q * 4);
        float4 gA = make_float4(0, 0, 0, 0), gB = make_float4(0, 0, 0, 0);
        #pragma unroll
        for (int z = 0; z < KSPLIT; z++) {
            if (iA < NE) {
                float4 p = *(const float4*)(g_part + ((size_t)z * NEP + iA) * 256 + 128 + c0 + q * 4);
                gA.x += p.x; gA.y += p.y; gA.z += p.z; gA.w += p.w;
            }
            if (iB < NE) {
                float4 p = *(const float4*)(g_part + ((size_t)z * NEP + iB) * 256 + 128 + c0 + q * 4);
                gB.x += p.x; gB.y += p.y; gB.z += p.z; gB.w += p.w;
            }
        }
        oA[q] = make_float4(bb.x + gA.x, bb.y + gA.y, bb.z + gA.z, bb.w + gA.w);
        oB[q] = make_float4(bb.x + gB.x, bb.y + gB.y, bb.z + gB.z, bb.w + gB.w);
    }
    #pragma unroll 4
    for (int kk = 0; kk < 128; kk++) {
        float evA = sE1[eA * 132 + kk];
        float evB = sE1[eB * 132 + kk];
        const float4* r2 = (const float4*)(root2 + kk * D + c0);
        #pragma unroll
        for (int q = 0; q < 4; q++) {
            float4 r = r2[q];
            oA[q].x += evA * r.x; oA[q].y += evA * r.y; oA[q].z += evA * r.z; oA[q].w += evA * r.w;
            oB[q].x += evB * r.x; oB[q].y += evB * r.y; oB[q].z += evB * r.z; oB[q].w += evB * r.w;
        }
    }
    if (iA < NE) {
        #pragma unroll
        for (int q = 0; q < 4; q++) *(float4*)(out + (size_t)iA * D + c0 + q * 4) = oA[q];
    }
    if (iB < NE) {
        #pragma unroll
        for (int q = 0; q < 4; q++) *(float4*)(out + (size_t)iB * D + c0 + q * 4) = oB[q];
    }
}

// ======================= launch =======================
extern "C" void kernel_launch(void* const* d_in, const int* in_sizes, int n_in,
                              void* d_out, int out_size) {
    const float* xe    = (const float*)d_in[0];
    const float* xm    = (const float*)d_in[1];
    const float* w     = (const float*)d_in[2];
    const float* W1    = (const float*)d_in[3];
    const float* root1 = (const float*)d_in[4];
    const float* b1    = (const float*)d_in[5];
    const float* W2    = (const float*)d_in[6];
    const float* root2 = (const float*)d_in[7];
    const float* b2    = (const float*)d_in[8];
    float* out = (float*)d_out;

    k_lev<<<NE, 256>>>(w);
    k_root1<<<NM / 16 + NE / 16, 128>>>(xm, xe, root1, b1);
    k_Z<<<dim3(NM / 16, 5), 256>>>(xm, W1, W2);

    cudaFuncSetAttribute(k_mma, cudaFuncAttributeMaxDynamicSharedMemorySize, SM_MMA_BYTES);
    k_mma<<<dim3(158, KSPLIT), 256, SM_MMA_BYTES>>>();

    cudaFuncSetAttribute(k_epi, cudaFuncAttributeMaxDynamicSharedMemorySize, SM_EPI_BYTES);
    k_epi<<<(NE + 63) / 64, 256, SM_EPI_BYTES>>>(root2, b2, out);
}

// round 16
// speedup vs baseline: 1.0234x; 1.0234x over previous
#include <cuda_runtime.h>
#include <cuda_fp16.h>
#include <cstdint>

#define NE 10000
#define NM 2048
#define D  128
#define NEP 10112            // 79*128 padded entity count
#define KSPLIT 8

// ======================= device scratch (no allocations allowed) ============
__device__ unsigned char g_lev[(size_t)NE * NM];   // 0 = no edge, 1..5 relation
__device__ __half g_invh[NE * 8];                  // [i][r] 1/cnt (fp16), r=0 -> 0
__device__ float g_m1[NM * D];                     // relu(x_m @ root1 + b1)
__device__ __half g_ZH[(size_t)5 * 256 * NM];      // [r][n][j] K-major fp16 B
__device__ float g_ebase[(size_t)NE * D];          // x_e @ root1 + b1
__device__ float g_part[(size_t)KSPLIT * NEP * 256];  // K-split partials

// ======================= small PTX helpers ============
#define CP_ASYNC16(s, g) asm volatile("cp.async.cg.shared.global [%0], [%1], 16;" :: "r"(s), "l"(g))
#define CP_COMMIT()      asm volatile("cp.async.commit_group;" ::: "memory")
#define CP_WAIT0()       asm volatile("cp.async.wait_group 0;" ::: "memory")
#define LDSM_X4(r0, r1, r2, r3, a)                                                   \
    asm volatile("ldmatrix.sync.aligned.m8n8.x4.shared.b16 {%0,%1,%2,%3}, [%4];"     \
                 : "=r"(r0), "=r"(r1), "=r"(r2), "=r"(r3) : "r"(a))

__device__ __forceinline__ uint32_t smem_u32(const void* p) {
    uint32_t a;
    asm("{ .reg .u64 t; cvta.to.shared.u64 t, %1; cvt.u32.u64 %0, t; }" : "=r"(a) : "l"(p));
    return a;
}

__device__ __forceinline__ void mma_f16(float* d, const uint32_t* a, uint32_t b0, uint32_t b1) {
    asm volatile(
        "mma.sync.aligned.m16n8k16.row.col.f32.f16.f16.f32 "
        "{%0,%1,%2,%3}, {%4,%5,%6,%7}, {%8,%9}, {%0,%1,%2,%3};"
        : "+f"(d[0]), "+f"(d[1]), "+f"(d[2]), "+f"(d[3])
        : "r"(a[0]), "r"(a[1]), "r"(a[2]), "r"(a[3]), "r"(b0), "r"(b1));
}

// ======================= kernel 1: prep = lev/inv + root1 transforms =========
// Block roles: [0, MBLK) mole-root1; [MBLK, MBLK+EBLK) entity-root1; rest: lev.
constexpr int MBLK = NM / 32;                  // 64
constexpr int EBLK = (NE + 31) / 32;           // 313
__global__ void k_prep(const float* __restrict__ w, const float* __restrict__ xm,
                       const float* __restrict__ xe, const float* __restrict__ root1,
                       const float* __restrict__ b1) {
    int bi = blockIdx.x;
    int tid = threadIdx.x;
    if (bi < MBLK + EBLK) {
        __shared__ float xs[128][36];
        bool mole = bi < MBLK;
        int r0 = mole ? bi * 32 : (bi - MBLK) * 32;
        const float* src = mole ? xm : xe;
        int nrow = mole ? NM : NE;
        for (int t = tid; t < 32 * 128; t += 256) {
            int e = t >> 7, k = t & 127;
            int rr = min(r0 + e, nrow - 1);
            xs[k][e] = src[(size_t)rr * D + k];
        }
        __syncthreads();
        int c = tid & 127, h = tid >> 7;
        int e0 = h * 16;
        float a[16];
        #pragma unroll
        for (int e = 0; e < 16; e++) a[e] = 0.0f;
        #pragma unroll 2
        for (int k = 0; k < 128; k++) {
            float wv = root1[k * D + c];
            float4 x0 = *(const float4*)&xs[k][e0];
            float4 x1 = *(const float4*)&xs[k][e0 + 4];
            float4 x2 = *(const float4*)&xs[k][e0 + 8];
            float4 x3 = *(const float4*)&xs[k][e0 + 12];
            a[0] += x0.x * wv; a[1] += x0.y * wv; a[2] += x0.z * wv; a[3] += x0.w * wv;
            a[4] += x1.x * wv; a[5] += x1.y * wv; a[6] += x1.z * wv; a[7] += x1.w * wv;
            a[8] += x2.x * wv; a[9] += x2.y * wv; a[10] += x2.z * wv; a[11] += x2.w * wv;
            a[12] += x3.x * wv; a[13] += x3.y * wv; a[14] += x3.z * wv; a[15] += x3.w * wv;
        }
        float bb = b1[c];
        if (mole) {
            #pragma unroll
            for (int e = 0; e < 16; e++)
                g_m1[(size_t)(r0 + e0 + e) * D + c] = fmaxf(a[e] + bb, 0.0f);
        } else {
            #pragma unroll
            for (int e = 0; e < 16; e++)
                if (r0 + e0 + e < NE) g_ebase[(size_t)(r0 + e0 + e) * D + c] = a[e] + bb;
        }
    } else {
        int i = bi - (MBLK + EBLK);
        __shared__ int scnt[5];
        if (tid < 5) scnt[tid] = 0;
        __syncthreads();
        int cnt[5] = {0, 0, 0, 0, 0};
        const float* wr = w + (size_t)i * NM;
        unsigned char* lr = g_lev + (size_t)i * NM;
        #pragma unroll
        for (int s = 0; s < 8; s++) {
            int j = tid + s * 256;
            float v = wr[j];
            int lv = (int)ceilf(v * 6.0f) - 1;
            int o = (lv >= 1 && lv <= 5) ? lv : 0;
            lr[j] = (unsigned char)o;
            if (o) cnt[o - 1]++;
        }
        #pragma unroll
        for (int r = 0; r < 5; r++) {
            int v = cnt[r];
            #pragma unroll
            for (int off = 16; off; off >>= 1) v += __shfl_down_sync(0xffffffffu, v, off);
            if ((tid & 31) == 0) atomicAdd(&scnt[r], v);
        }
        __syncthreads();
        if (tid < 8) {
            float iv = 0.0f;
            if (tid >= 1 && tid <= 5) {
                int c = scnt[tid - 1];
                iv = (c > 0) ? 1.0f / (float)c : 0.0f;
            }
            g_invh[i * 8 + tid] = __float2half(iv);
        }
    }
}

// ======================= kernel 4: ZH[r][n][j] = fp16 K-major ================
__global__ void k_Z(const float* __restrict__ xm, const float* __restrict__ W1,
                    const float* __restrict__ W2) {
    __shared__ float xs[128][20], ms[128][20];
    int ri = blockIdx.y;
    int j0 = blockIdx.x * 16;
    for (int t = threadIdx.x; t < 16 * 128; t += 256) {
        int e = t >> 7, k = t & 127;
        xs[k][e] = xm[(size_t)(j0 + e) * D + k];
        ms[k][e] = g_m1[(size_t)(j0 + e) * D + k];
    }
    __syncthreads();
    int c = threadIdx.x;
    int cc = c & 127;
    const float* W = ((c < 128) ? W1 : W2) + (size_t)(ri + 1) * D * D;
    const float(*S)[20] = (c < 128) ? xs : ms;
    float a[16];
    #pragma unroll
    for (int e = 0; e < 16; e++) a[e] = 0.0f;
    #pragma unroll 2
    for (int k = 0; k < 128; k++) {
        float wv = W[k * D + cc];
        float4 x0 = *(const float4*)&S[k][0];
        float4 x1 = *(const float4*)&S[k][4];
        float4 x2 = *(const float4*)&S[k][8];
        float4 x3 = *(const float4*)&S[k][12];
        a[0] += x0.x * wv; a[1] += x0.y * wv; a[2] += x0.z * wv; a[3] += x0.w * wv;
        a[4] += x1.x * wv; a[5] += x1.y * wv; a[6] += x1.z * wv; a[7] += x1.w * wv;
        a[8] += x2.x * wv; a[9] += x2.y * wv; a[10] += x2.z * wv; a[11] += x2.w * wv;
        a[12] += x3.x * wv; a[13] += x3.y * wv; a[14] += x3.z * wv; a[15] += x3.w * wv;
    }
    __half2* dst = (__half2*)(g_ZH + ((size_t)ri * 256 + c) * NM + j0);
    #pragma unroll
    for (int e = 0; e < 8; e++) dst[e] = __floats2half2_rn(a[2 * e], a[2 * e + 1]);
}

// ======================= kernel 5: fp16 mask-GEMM, M64 x N256 CTA tile =======
constexpr int KT = 64;
constexpr int KQ = 10240 / KSPLIT;             // 1280
constexpr int ITERS = KQ / KT;                 // 20
constexpr int ASTR = 72;
constexpr int A_H = 64 * ASTR;
constexpr int B_H = 256 * ASTR;
constexpr int STAGE_H = A_H + B_H;
constexpr int STAGE_B = STAGE_H * 2;
constexpr int SM_MMA_BYTES = 2 * STAGE_B;      // 92160 bytes

__global__ __launch_bounds__(256, 2) void k_mma() {
    extern __shared__ __half smh[];
    uint32_t sbase = smem_u32(smh);

    int tid = threadIdx.x;
    int wid = tid >> 5, lane = tid & 31;
    int gid = lane >> 2, t4 = lane & 3;
    int wm = wid & 1, wn = wid >> 1;

    int i0 = blockIdx.x * 64;
    int kbase = blockIdx.y * KQ;

    int arow = tid >> 2, aq = tid & 3;
    int gr = min(i0 + arow, NE - 1);
    const unsigned char* levrow = g_lev + (size_t)gr * NM;
    const __half* invrow = g_invh + (size_t)gr * 8;

    auto buildA = [&](int s, int r, int j0) {
        unsigned char rv = (unsigned char)(r + 1);
        uint4 u = *(const uint4*)(levrow + j0 + aq * 16);
        unsigned char bts[16];
        *(uint4*)bts = u;
        __half ivh = invrow[r + 1];
        __half z = __ushort_as_half((unsigned short)0);
        uint32_t pk[8];
        #pragma unroll
        for (int q = 0; q < 8; q++) {
            __half2 h2;
            h2.x = (bts[2 * q] == rv) ? ivh : z;
            h2.y = (bts[2 * q + 1] == rv) ? ivh : z;
            pk[q] = *(uint32_t*)&h2;
        }
        uint32_t* dst = (uint32_t*)(smh + s * STAGE_H + arow * ASTR + aq * 16);
        *(uint4*)dst = make_uint4(pk[0], pk[1], pk[2], pk[3]);
        *(uint4*)(dst + 4) = make_uint4(pk[4], pk[5], pk[6], pk[7]);
    };
    auto stageB = [&](int s, int r, int j0) {
        uint32_t sb = sbase + s * STAGE_B + A_H * 2;
        const __half* gb = g_ZH + (size_t)r * 256 * NM + j0;
        #pragma unroll
        for (int h = 0; h < 8; h++) {
            int c = tid + h * 256;
            int n = c >> 3, ch = c & 7;
            uint32_t sa = sb + (uint32_t)(n * (ASTR * 2) + ch * 16);
            CP_ASYNC16(sa, gb + (size_t)n * NM + ch * 8);
        }
        CP_COMMIT();
    };

    uint32_t aAddr[2], bAddr[4];
    #pragma unroll
    for (int mi = 0; mi < 2; mi++) {
        int row = wm * 32 + mi * 16 + (lane & 15);
        aAddr[mi] = sbase + (uint32_t)(row * ASTR + (lane >> 4) * 8) * 2u;
    }
    #pragma unroll
    for (int nj = 0; nj < 4; nj++) {
        int nrow = wn * 64 + nj * 16 + ((lane >> 4) & 1) * 8 + (lane & 7);
        int koff = ((lane >> 3) & 1) * 8;
        bAddr[nj] = sbase + (uint32_t)(A_H * 2) + (uint32_t)(nrow * ASTR + koff) * 2u;
    }

    float dacc[2][8][4];
    #pragma unroll
    for (int mi = 0; mi < 2; mi++)
        #pragma unroll
        for (int ni = 0; ni < 8; ni++)
            #pragma unroll
            for (int q = 0; q < 4; q++) dacc[mi][ni][q] = 0.0f;

    {
        int kg = kbase;
        stageB(0, kg >> 11, kg & 2047);
        buildA(0, kg >> 11, kg & 2047);
    }

    for (int it = 0; it < ITERS; it++) {
        int s = it & 1;
        CP_WAIT0();
        __syncthreads();
        if (it + 1 < ITERS) {
            int kg = kbase + (it + 1) * KT;
            stageB(s ^ 1, kg >> 11, kg & 2047);
            buildA(s ^ 1, kg >> 11, kg & 2047);
        }

        uint32_t soff = (uint32_t)(s * STAGE_B);
        #pragma unroll
        for (int kk = 0; kk < 4; kk++) {
            uint32_t kb = soff + kk * 32;
            uint32_t af[2][4];
            #pragma unroll
            for (int mi = 0; mi < 2; mi++)
                LDSM_X4(af[mi][0], af[mi][1], af[mi][2], af[mi][3], aAddr[mi] + kb);
            #pragma unroll
            for (int nj = 0; nj < 4; nj++) {
                uint32_t r0, r1, r2, r3;
                LDSM_X4(r0, r1, r2, r3, bAddr[nj] + kb);
                #pragma unroll
                for (int mi = 0; mi < 2; mi++) {
                    mma_f16(dacc[mi][2 * nj], af[mi], r0, r1);
                    mma_f16(dacc[mi][2 * nj + 1], af[mi], r2, r3);
                }
            }
        }
        __syncthreads();
    }

    float* dst = g_part + (size_t)blockIdx.y * NEP * 256;
    #pragma unroll
    for (int mi = 0; mi < 2; mi++) {
        int r0 = i0 + wm * 32 + mi * 16 + gid;
        #pragma unroll
        for (int ni = 0; ni < 8; ni++) {
            int cn = wn * 64 + ni * 8 + 2 * t4;
            *(float2*)(dst + (size_t)r0 * 256 + cn) = make_float2(dacc[mi][ni][0], dacc[mi][ni][1]);
            *(float2*)(dst + (size_t)(r0 + 8) * 256 + cn) = make_float2(dacc[mi][ni][2], dacc[mi][ni][3]);
        }
    }
}

// ======================= kernel 6: reduce partials + both conv epilogues =====
constexpr int SM_EPI_BYTES = 64 * 132 * 4;
__global__ __launch_bounds__(256, 1) void k_epi(const float* __restrict__ root2,
                                                const float* __restrict__ b2,
                                                float* __restrict__ out) {
    extern __shared__ float sE1[];   // [64][132]
    int i0 = blockIdx.x * 64;
    int tid = threadIdx.x;

    for (int idx = tid; idx < 64 * 32; idx += 256) {
        int e = idx >> 5, q = idx & 31;
        int i = i0 + e;
        float4 v = make_float4(0, 0, 0, 0);
        if (i < NE) {
            float4 s = *(const float4*)(g_ebase + (size_t)i * D + q * 4);
            #pragma unroll
            for (int z = 0; z < KSPLIT; z++) {
                float4 p = *(const float4*)(g_part + ((size_t)z * NEP + i) * 256 + q * 4);
                s.x += p.x; s.y += p.y; s.z += p.z; s.w += p.w;
            }
            v.x = fmaxf(s.x, 0.0f); v.y = fmaxf(s.y, 0.0f);
            v.z = fmaxf(s.z, 0.0f); v.w = fmaxf(s.w, 0.0f);
        }
        *(float4*)(sE1 + e * 132 + q * 4) = v;
    }
    __syncthreads();

    int pe = tid >> 3, cg = tid & 7;
    int eA = pe * 2, eB = pe * 2 + 1;
    int iA = i0 + eA, iB = i0 + eB;
    int c0 = cg * 16;
    float4 oA[4], oB[4];
    #pragma unroll
    for (int q = 0; q < 4; q++) {
        float4 bb = *(const float4*)(b2 + c0 + q * 4);
        float4 gA = make_float4(0, 0, 0, 0), gB = make_float4(0, 0, 0, 0);
        #pragma unroll
        for (int z = 0; z < KSPLIT; z++) {
            if (iA < NE) {
                float4 p = *(const float4*)(g_part + ((size_t)z * NEP + iA) * 256 + 128 + c0 + q * 4);
                gA.x += p.x; gA.y += p.y; gA.z += p.z; gA.w += p.w;
            }
            if (iB < NE) {
                float4 p = *(const float4*)(g_part + ((size_t)z * NEP + iB) * 256 + 128 + c0 + q * 4);
                gB.x += p.x; gB.y += p.y; gB.z += p.z; gB.w += p.w;
            }
        }
        oA[q] = make_float4(bb.x + gA.x, bb.y + gA.y, bb.z + gA.z, bb.w + gA.w);
        oB[q] = make_float4(bb.x + gB.x, bb.y + gB.y, bb.z + gB.z, bb.w + gB.w);
    }
    #pragma unroll 4
    for (int kk = 0; kk < 128; kk++) {
        float evA = sE1[eA * 132 + kk];
        float evB = sE1[eB * 132 + kk];
        const float4* r2 = (const float4*)(root2 + kk * D + c0);
        #pragma unroll
        for (int q = 0; q < 4; q++) {
            float4 r = r2[q];
            oA[q].x += evA * r.x; oA[q].y += evA * r.y; oA[q].z += evA * r.z; oA[q].w += evA * r.w;
            oB[q].x += evB * r.x; oB[q].y += evB * r.y; oB[q].z += evB * r.z; oB[q].w += evB * r.w;
        }
    }
    if (iA < NE) {
        #pragma unroll
        for (int q = 0; q < 4; q++) *(float4*)(out + (size_t)iA * D + c0 + q * 4) = oA[q];
    }
    if (iB < NE) {
        #pragma unroll
        for (int q = 0; q < 4; q++) *(float4*)(out + (size_t)iB * D + c0 + q * 4) = oB[q];
    }
}

// ======================= launch =======================
extern "C" void kernel_launch(void* const* d_in, const int* in_sizes, int n_in,
                              void* d_out, int out_size) {
    const float* xe    = (const float*)d_in[0];
    const float* xm    = (const float*)d_in[1];
    const float* w     = (const float*)d_in[2];
    const float* W1    = (const float*)d_in[3];
    const float* root1 = (const float*)d_in[4];
    const float* b1    = (const float*)d_in[5];
    const float* W2    = (const float*)d_in[6];
    const float* root2 = (const float*)d_in[7];
    const float* b2    = (const float*)d_in[8];
    float* out = (float*)d_out;

    k_prep<<<MBLK + EBLK + NE, 256>>>(w, xm, xe, root1, b1);
    k_Z<<<dim3(NM / 16, 5), 256>>>(xm, W1, W2);

    cudaFuncSetAttribute(k_mma, cudaFuncAttributeMaxDynamicSharedMemorySize, SM_MMA_BYTES);
    k_mma<<<dim3(158, KSPLIT), 256, SM_MMA_BYTES>>>();

    cudaFuncSetAttribute(k_epi, cudaFuncAttributeMaxDynamicSharedMemorySize, SM_EPI_BYTES);
    k_epi<<<(NE + 63) / 64, 256, SM_EPI_BYTES>>>(root2, b2, out);
}